// round 9
// baseline (speedup 1.0000x reference)
#include <cuda_runtime.h>

// Problem constants (fixed by reference hparams)
#define BB     32          // batch
#define NSEG   108         // MAX_NUM_SEG
#define NTOT   3456        // BB*NSEG
#define SS     64          // candidates per segment
#define TX     2560        // MAX_LEN_PAD
#define D4     20          // feature dim / 4 (float4 units)
#define MINSEG 19
#define PMAX   (NTOT * SS) // 221184 max compacted rows

// Scratch (no allocations allowed -> __device__ globals)
__device__ int4 g_seginfo[NTOT];   // per segment: {abs_base, cnt, off, scale_bits}
__device__ int  g_rows;            // total / BB
__device__ int2 g_meta[PMAX];      // per compacted row: {src_row, lam bits}

// ---------------------------------------------------------------------------
// shfl exclusive warp scan; returns exclusive prefix, sets warp total
// ---------------------------------------------------------------------------
__device__ __forceinline__ int warp_excl(int v, int lane, int& tot) {
    int x = v;
#pragma unroll
    for (int o = 1; o < 32; o <<= 1) {
        int y = __shfl_up_sync(0xffffffffu, x, o);
        if (lane >= o) x += y;
    }
    tot = __shfl_sync(0xffffffffu, x, 31);
    return x - v;
}

// Masked count for one segment: #{ s in [0,64) : floor(rn(s/scale)) < L }.
// Estimate seed + exact __fdiv_rn verification -> bit-exact vs reference.
__device__ __forceinline__ int seg_cnt(int len, int lseq, int off, float scale) {
    const int L = min(len - 1, lseq - 1 - off);
    if (L <= 0) return 0;
    const float Lf = (float)L;
    int s = (int)(Lf * scale);             // seed near the boundary
    if (s > 63) s = 63;
    while (s > 0 && !(floorf(__fdiv_rn((float)s, scale)) < Lf)) s--;
    while (s < 63 && (floorf(__fdiv_rn((float)(s + 1), scale)) < Lf)) s++;
    return s + 1;                          // cond(0) true since L>0
}

// ---------------------------------------------------------------------------
// Kernel 1: ONE block, 1024 threads = 32 warps; warp b owns batch b.
//   per warp : vector-load 4 segs/lane, shfl scan len_seg -> offsets,
//              counts, shfl scan counts -> local bases + batch total
//   block    : one smem exchange, warp 0 scans the 32 batch totals
//   output   : g_seginfo[n] = {absolute base, cnt, off, scale bits}, g_rows
// ---------------------------------------------------------------------------
__global__ void __launch_bounds__(1024) k_seg(const int* __restrict__ len_seq,
                                              const float* __restrict__ scales_u,
                                              const int* __restrict__ len_seg_raw) {
    __shared__ int sbt[BB];      // per-batch count totals
    __shared__ int sbase[BB];    // exclusive bases
    __shared__ int stotal;

    const int tid = threadIdx.x;
    const int lane = tid & 31;
    const int b = tid >> 5;                 // warp id = batch id
    const bool act = lane < NSEG / 4;       // 27 active lanes per warp

    // issue all loads first (independent -> MLP hides cold DRAM latency)
    int4 lr = make_int4(-MINSEG, -MINSEG, -MINSEG, -MINSEG);
    float4 sc = make_float4(0.5f, 0.5f, 0.5f, 0.5f);
    const int vidx = b * (NSEG / 4) + lane;
    if (act) {
        lr = ((const int4*)len_seg_raw)[vidx];
        sc = ((const float4*)scales_u)[vidx];
    }
    const int lseq = len_seq[b];

    const int l0 = lr.x + MINSEG, l1 = lr.y + MINSEG;
    const int l2 = lr.z + MINSEG, l3 = lr.w + MINSEG;
    const float s0 = sc.x + 0.5f, s1 = sc.y + 0.5f;
    const float s2 = sc.z + 0.5f, s3 = sc.w + 0.5f;

    // scan #1: len_seg -> offsets
    int tot;
    const int ex = warp_excl(l0 + l1 + l2 + l3, lane, tot);
    const int o0 = ex, o1 = ex + l0, o2 = o1 + l1, o3 = o2 + l2;

    // counts (ILP across 4 segments)
    const int c0 = seg_cnt(l0, lseq, o0, s0);
    const int c1 = seg_cnt(l1, lseq, o1, s1);
    const int c2 = seg_cnt(l2, lseq, o2, s2);
    const int c3 = seg_cnt(l3, lseq, o3, s3);

    // scan #2: counts -> local bases + batch total
    int ctot;
    const int cex = warp_excl(c0 + c1 + c2 + c3, lane, ctot);

    if (lane == 0) sbt[b] = ctot;
    __syncthreads();
    if (b == 0) {
        int t;
        int e = warp_excl(sbt[lane], lane, t);
        sbase[lane] = e;
        if (lane == 31) stotal = t;
    }
    __syncthreads();

    if (act) {
        const int bb = sbase[b];
        const int n0 = b * NSEG + lane * 4;
        g_seginfo[n0 + 0] = make_int4(bb + cex,               c0, o0, __float_as_int(s0));
        g_seginfo[n0 + 1] = make_int4(bb + cex + c0,          c1, o1, __float_as_int(s1));
        g_seginfo[n0 + 2] = make_int4(bb + cex + c0 + c1,     c2, o2, __float_as_int(s2));
        g_seginfo[n0 + 3] = make_int4(bb + cex + c0 + c1 + c2, c3, o3, __float_as_int(s3));
    }
    if (tid == 0) g_rows = stotal / BB;
}

// ---------------------------------------------------------------------------
// Kernel 2: per-compacted-row metadata scatter. 432 blocks x 256 threads,
// one warp per segment. ONE int4 load gives everything; no prologue, no smem,
// no barriers. Each segment scatters its cnt<=64 rows ({src_row, lambda}) to
// its KNOWN absolute destination range - no search anywhere.
// ---------------------------------------------------------------------------
__global__ void __launch_bounds__(256) k_rowmeta() {
    const int n = blockIdx.x * 8 + (threadIdx.x >> 5);   // 8 warps -> 8 segments
    const int lane = threadIdx.x & 31;

    const int4 si = g_seginfo[n];          // {base, cnt, off, scale_bits}
    const int cnt = si.y;
    if (cnt == 0) return;

    const int   base  = si.x;
    const int   off   = si.z;
    const float scale = __int_as_float(si.w);
    const int   bTX   = (n / NSEG) * TX;

#pragma unroll
    for (int s = lane; s < cnt; s += 32) {   // cnt <= 64 -> at most 2 iters
        const float v  = __fdiv_rn((float)s, scale);
        const float fl = floorf(v);
        const float lam = v - fl;
        int i = (int)fl + off;               // exact small ints
        if (i > TX - 2) i = TX - 2;
        if (i < 0) i = 0;
        g_meta[base + s] = make_int2(bTX + i, __float_as_int(lam));
    }
}

// ---------------------------------------------------------------------------
// Kernel 3: barrier-free flat gather. One thread = one output float4.
// All indices fit in 32-bit (max 1.6M) -> pure int addressing. meta[p] is
// L1-broadcast across the 20 threads of a row; x reads coalesced per row;
// stores perfectly coalesced. No smem, no syncs.
// ---------------------------------------------------------------------------
__global__ void __launch_bounds__(256) k_gather(const float* __restrict__ x,
                                                float* __restrict__ out) {
    const int gid = blockIdx.x * 256 + threadIdx.x;  // < 32*2560*20 = 1.6M
    const int row = gid / D4;
    const int d4  = gid - row * D4;
    const int b   = row / TX;
    const int t   = row - b * TX;

    float4 res = make_float4(0.f, 0.f, 0.f, 0.f);
    const int rows = g_rows;
    if (t < rows) {
        const int p = b * rows + t;
        const int2 m = g_meta[p];
        const float lam = __int_as_float(m.y);
        const float om  = 1.0f - lam;
        const float4* __restrict__ x4 = (const float4*)x;
        const int sbase = m.x * D4 + d4;               // < 1.64M, fits int
        const float4 a = x4[sbase];
        const float4 c = x4[sbase + D4];
        res.x = om * a.x + lam * c.x;
        res.y = om * a.y + lam * c.y;
        res.z = om * a.z + lam * c.z;
        res.w = om * a.w + lam * c.w;
    }
    ((float4*)out)[gid] = res;
}

// ---------------------------------------------------------------------------
extern "C" void kernel_launch(void* const* d_in, const int* in_sizes, int n_in,
                              void* d_out, int out_size) {
    const float* x           = (const float*)d_in[0];  // (32, 2560, 80) f32
    const int*   len_seq     = (const int*)d_in[1];    // (32,) i32
    const float* scales_u    = (const float*)d_in[2];  // (3456,) f32
    const int*   len_seg_raw = (const int*)d_in[3];    // (3456,) i32
    float*       out         = (float*)d_out;          // (32, 2560, 80) f32

    k_seg<<<1, 1024>>>(len_seq, scales_u, len_seg_raw);
    k_rowmeta<<<NTOT / 8, 256>>>();
    k_gather<<<(BB * TX * D4) / 256, 256>>>(x, out);
}